// round 1
// baseline (speedup 1.0000x reference)
#include <cuda_runtime.h>
#include <cuda_bf16.h>

// TTTConv: causal depthwise conv1d
//   x:           (B, N, D) fp32,  B=4, N=4096, D=2048
//   conv_weight: (D, K)    fp32,  K=4
//   conv_bias:   (D,)      fp32
// Outputs (concatenated into d_out):
//   conv_output: (B, N, D)   out[b,n,d] = sum_k x[b, n-(K-1)+k, d] * w[d,k] + bias[d]
//                             (zero-padded on the left; XLA conv = correlation, no flip)
//   conv_states: (B, D, K)   states[b,d,k] = x[b, N-K+k, d]

#define Bc 4
#define Nc 4096
#define Dc 2048
#define Kc 4
#define NT 32          // time steps per thread
#define DV (Dc / 4)    // float4 groups along D = 512

__global__ void __launch_bounds__(256) ttt_conv_main(
    const float* __restrict__ x,
    const float* __restrict__ w,
    const float* __restrict__ bias,
    float* __restrict__ out)
{
    int tid  = blockIdx.x * blockDim.x + threadIdx.x;
    int dvec = tid % DV;                 // float4 group along D
    int nt   = (tid / DV) % (Nc / NT);   // time tile
    int b    = tid / (DV * (Nc / NT));   // batch
    int d    = dvec * 4;
    int n0   = nt * NT;

    // Per-thread constants: 4 channels x 4 taps + bias
    float4 wv0 = ((const float4*)w)[d + 0];  // w[d+0][0..3]
    float4 wv1 = ((const float4*)w)[d + 1];
    float4 wv2 = ((const float4*)w)[d + 2];
    float4 wv3 = ((const float4*)w)[d + 3];
    float4 bv  = ((const float4*)bias)[dvec];

    const float4* xb = (const float4*)(x   + (size_t)b * Nc * Dc) + dvec;
    float4*       ob = (float4*)      (out + (size_t)b * Nc * Dc) + dvec;

    // Sliding window: x at n-3, n-2, n-1
    float4 xm3, xm2, xm1;
    if (n0 == 0) {
        xm3 = make_float4(0.f, 0.f, 0.f, 0.f);
        xm2 = xm3;
        xm1 = xm3;
    } else {
        xm3 = xb[(size_t)(n0 - 3) * DV];
        xm2 = xb[(size_t)(n0 - 2) * DV];
        xm1 = xb[(size_t)(n0 - 1) * DV];
    }

#pragma unroll 8
    for (int n = n0; n < n0 + NT; ++n) {
        float4 xc = xb[(size_t)n * DV];
        float4 r;
        r.x = fmaf(xm3.x, wv0.x, fmaf(xm2.x, wv0.y, fmaf(xm1.x, wv0.z, fmaf(xc.x, wv0.w, bv.x))));
        r.y = fmaf(xm3.y, wv1.x, fmaf(xm2.y, wv1.y, fmaf(xm1.y, wv1.z, fmaf(xc.y, wv1.w, bv.y))));
        r.z = fmaf(xm3.z, wv2.x, fmaf(xm2.z, wv2.y, fmaf(xm1.z, wv2.z, fmaf(xc.z, wv2.w, bv.z))));
        r.w = fmaf(xm3.w, wv3.x, fmaf(xm2.w, wv3.y, fmaf(xm1.w, wv3.z, fmaf(xc.w, wv3.w, bv.w))));
        ob[(size_t)n * DV] = r;
        xm3 = xm2; xm2 = xm1; xm1 = xc;
    }
}

// conv_states[b, d, k] = x[b, N-K+k, d]   — tiny (128 KB), separate kernel
__global__ void __launch_bounds__(256) ttt_conv_states(
    const float* __restrict__ x,
    float* __restrict__ states)
{
    int i = blockIdx.x * blockDim.x + threadIdx.x;
    if (i >= Bc * Dc * Kc) return;
    int b   = i / (Dc * Kc);
    int rem = i % (Dc * Kc);
    int d   = rem / Kc;
    int k   = rem % Kc;
    states[i] = x[(size_t)b * Nc * Dc + (size_t)(Nc - Kc + k) * Dc + d];
}

extern "C" void kernel_launch(void* const* d_in, const int* in_sizes, int n_in,
                              void* d_out, int out_size)
{
    const float* x    = (const float*)d_in[0];
    const float* w    = (const float*)d_in[1];
    const float* bias = (const float*)d_in[2];
    float* out = (float*)d_out;

    // Main conv: Bc * (Nc/NT) * DV threads = 4 * 128 * 512 = 262144
    int total = Bc * (Nc / NT) * DV;
    ttt_conv_main<<<total / 256, 256>>>(x, w, bias, out);

    // States appended after conv_output
    float* states = out + (size_t)Bc * Nc * Dc;
    int ns = Bc * Dc * Kc;
    ttt_conv_states<<<(ns + 255) / 256, 256>>>(x, states);
}